// round 6
// baseline (speedup 1.0000x reference)
#include <cuda_runtime.h>
#include <cuda_fp16.h>
#include <stdint.h>

#define NN 4096
#define FC 256      // F_IN == F_OUT
#define BB 8
#define WORDS (NN / 32)

// ---------------- scratch (no allocations allowed) ----------------
__device__ uint32_t g_adj[NN * WORDS];            // 2 MB bitmask adjacency
__device__ __half   g_xt[(size_t)BB * NN * FC];   // 16 MB: xt = x @ W (fp16)
__device__ __half   g_wh[FC * FC];                // 128 KB: W^T as fp16 [n][k]

// =================== setup kernels ===================
__global__ void k_clear_adj() {
    int i = blockIdx.x * blockDim.x + threadIdx.x;
    if (i < NN * WORDS) g_adj[i] = 0u;
}
__global__ void k_scatter(const int* __restrict__ ei, int E) {
    int e = blockIdx.x * blockDim.x + threadIdx.x;
    if (e < E) {
        int src = ei[e];
        int dst = ei[E + e];
        atomicOr(&g_adj[src * WORDS + (dst >> 5)], 1u << (dst & 31));
    }
}
// W[k][n] -> g_wh[n][k] fp16 (tiled transpose, coalesced)
__global__ void k_wt(const float* __restrict__ W) {
    __shared__ float tile[32][33];
    const int bn = blockIdx.x * 32;
    const int bk = blockIdx.y * 32;
    const int tx = threadIdx.x, ty = threadIdx.y;
#pragma unroll
    for (int r = ty; r < 32; r += 8)
        tile[r][tx] = W[(size_t)(bk + r) * FC + bn + tx];
    __syncthreads();
#pragma unroll
    for (int r = ty; r < 32; r += 8)
        g_wh[(size_t)(bn + r) * FC + bk + tx] = __float2half_rn(tile[tx][r]);
}

// =================== mma / cp.async helpers ===================
__device__ __forceinline__ void mma_f16(float* d, const uint32_t* a, const uint32_t* b) {
    asm volatile(
        "mma.sync.aligned.m16n8k16.row.col.f32.f16.f16.f32 "
        "{%0,%1,%2,%3}, {%4,%5,%6,%7}, {%8,%9}, {%0,%1,%2,%3};"
        : "+f"(d[0]), "+f"(d[1]), "+f"(d[2]), "+f"(d[3])
        : "r"(a[0]), "r"(a[1]), "r"(a[2]), "r"(a[3]),
          "r"(b[0]), "r"(b[1]));
}
__device__ __forceinline__ uint32_t smem_u32(const void* p) {
    uint32_t a;
    asm("{ .reg .u64 t; cvta.to.shared.u64 t, %1; cvt.u32.u64 %0, t; }" : "=r"(a) : "l"(p));
    return a;
}
__device__ __forceinline__ uint32_t pack_h2(float x, float y) {
    __half2 h = __floats2half2_rn(x, y);
    return *(uint32_t*)&h;
}
#define CP_ASYNC16(dst, src) \
    asm volatile("cp.async.cg.shared.global [%0], [%1], 16;" :: "r"(dst), "l"(src))
#define CP_COMMIT() asm volatile("cp.async.commit_group;" ::: "memory")
#define CP_WAITN(n) asm volatile("cp.async.wait_group %0;" :: "n"(n) : "memory")

// XOR-swizzled word index inside one 128x32 fp32 tile (A).
#define SWX(row, k) ((row) * 32 + ((k) ^ (((row) & 7) << 2)))

// =================== kernel: xt = x @ W  (fp16 m16n8k16 mma, 3-stage cp.async) ===================
#define BM 128
#define BN 128
#define BK 32
#define NCH (FC / BK)          // 8
#define A_TILE_W  (128 * 32)   // 4096 words per A stage (fp32)
#define B_ROW_W   20           // B row stride: 80 bytes (32 halves = 64B + 16B pad)
#define B_TILE_W  (128 * B_ROW_W)  // 2560 words per B stage
#define A_OFF(p)  ((p) * A_TILE_W)
#define B_BASE    (3 * A_TILE_W)
#define B_OFF(p)  (B_BASE + (p) * B_TILE_W)
#define GEMM_SMEM ((3 * A_TILE_W + 3 * B_TILE_W) * 4)   // 79872 B

__global__ __launch_bounds__(256, 2) void k_gemm(const float* __restrict__ A) {
    extern __shared__ uint32_t sm[];
    const uint32_t sb = smem_u32(sm);

    const int tid  = threadIdx.x;
    const int lane = tid & 31;
    const int wid  = tid >> 5;
    const int wm = (wid & 1) * 64;
    const int wn = (wid >> 1) * 32;
    const int bm = blockIdx.x * BM;
    const int bn = blockIdx.y * BN;
    const int g  = lane >> 2;
    const int tg = lane & 3;

    // A cp.async mapping: id = q*256+tid -> row=id>>3 (32/pass), 16B chunk (id&7)*4 words
    const int a_row = tid >> 3;
    const int a_t4  = (tid & 7) * 4;
    // B cp.async mapping: id = q*256+tid -> row=id>>2 (64/pass), chunk (id&3)*8 halves
    const int b_row = tid >> 2;
    const int b_c8  = (tid & 3) * 8;

    float acc[4][4][4];
#pragma unroll
    for (int mt = 0; mt < 4; mt++)
#pragma unroll
        for (int nt = 0; nt < 4; nt++)
#pragma unroll
            for (int r = 0; r < 4; r++) acc[mt][nt][r] = 0.0f;

    auto issue = [&](int c, int p) {
        const int k0 = c * BK;
#pragma unroll
        for (int q = 0; q < 4; q++) {               // A: 128 rows x 32 fp32
            int m = q * 32 + a_row;
            uint32_t dst = sb + (A_OFF(p) + SWX(m, a_t4)) * 4;
            CP_ASYNC16(dst, &A[(size_t)(bm + m) * FC + k0 + a_t4]);
        }
#pragma unroll
        for (int q = 0; q < 2; q++) {               // B: 128 rows x 32 fp16
            int n = q * 64 + b_row;
            uint32_t dst = sb + (B_OFF(p) + n * B_ROW_W + (b_c8 >> 1)) * 4;
            CP_ASYNC16(dst, &g_wh[(size_t)(bn + n) * FC + k0 + b_c8]);
        }
        CP_COMMIT();
    };

    issue(0, 0);
    issue(1, 1);

#pragma unroll
    for (int c = 0; c < NCH; c++) {
        if (c + 2 < NCH) issue(c + 2, (c + 2) % 3);
        if (c < NCH - 2)      CP_WAITN(2);
        else if (c == NCH - 2) CP_WAITN(1);
        else                   CP_WAITN(0);
        __syncthreads();

        const int p = c % 3;
        const float*    Asf = (const float*)(sm + A_OFF(p));
        const uint32_t* Bs  = sm + B_OFF(p);

#pragma unroll
        for (int s2 = 0; s2 < 2; s2++) {            // 2 x K=16 per chunk
            const int kof = s2 * 16 + tg * 2;
            uint32_t a[4][4], b[4][2];
#pragma unroll
            for (int mt = 0; mt < 4; mt++) {
                int r0 = wm + mt * 16 + g;
                int r1 = r0 + 8;
                float2 v00 = *(const float2*)&Asf[r0 * 32 + (kof       ^ ((r0 & 7) << 2))];
                float2 v10 = *(const float2*)&Asf[r1 * 32 + (kof       ^ ((r1 & 7) << 2))];
                float2 v01 = *(const float2*)&Asf[r0 * 32 + ((kof + 8) ^ ((r0 & 7) << 2))];
                float2 v11 = *(const float2*)&Asf[r1 * 32 + ((kof + 8) ^ ((r1 & 7) << 2))];
                a[mt][0] = pack_h2(v00.x, v00.y);
                a[mt][1] = pack_h2(v10.x, v10.y);
                a[mt][2] = pack_h2(v01.x, v01.y);
                a[mt][3] = pack_h2(v11.x, v11.y);
            }
#pragma unroll
            for (int nt = 0; nt < 4; nt++) {
                int cc = wn + nt * 8 + g;
                b[nt][0] = Bs[cc * B_ROW_W + s2 * 8 + tg];
                b[nt][1] = Bs[cc * B_ROW_W + s2 * 8 + tg + 4];
            }
#pragma unroll
            for (int mt = 0; mt < 4; mt++)
#pragma unroll
                for (int nt = 0; nt < 4; nt++)
                    mma_f16(acc[mt][nt], a[mt], b[nt]);
        }
        __syncthreads();
    }

    // ---- epilogue: fp32 acc -> fp16 g_xt ----
#pragma unroll
    for (int mt = 0; mt < 4; mt++) {
#pragma unroll
        for (int nt = 0; nt < 4; nt++) {
            int r = bm + wm + mt * 16 + g;
            int c = bn + wn + nt * 8 + tg * 2;
            __half2 h01 = __floats2half2_rn(acc[mt][nt][0], acc[mt][nt][1]);
            __half2 h23 = __floats2half2_rn(acc[mt][nt][2], acc[mt][nt][3]);
            *(__half2*)&g_xt[(size_t)r * FC + c]       = h01;
            *(__half2*)&g_xt[(size_t)(r + 8) * FC + c] = h23;
        }
    }
}

// =================== kernel: aggregate ===================
// thread t: batch b = t>>5, features f8 = (t&31)*8 .. +7 (one LDG.128 / neighbor)
__global__ __launch_bounds__(256) void k_aggregate(const float* __restrict__ bias,
                                                   float* __restrict__ out) {
    __shared__ int s_nbr[NN];
    __shared__ int s_off[WORDS];
    __shared__ int s_total;

    const int i = blockIdx.x;
    const int t = threadIdx.x;
    const int b  = t >> 5;
    const int f8 = (t & 31) * 8;

    uint32_t word = (t < WORDS) ? g_adj[i * WORDS + t] : 0u;
    if (t < WORDS) s_off[t] = __popc(word);
    __syncthreads();

    if (t < 32) {   // warp 0: exclusive scan of 128 popcounts
        int v0 = s_off[4 * t], v1 = s_off[4 * t + 1];
        int v2 = s_off[4 * t + 2], v3 = s_off[4 * t + 3];
        int sum = v0 + v1 + v2 + v3;
        int inc = sum;
#pragma unroll
        for (int d = 1; d < 32; d <<= 1) {
            int x = __shfl_up_sync(0xFFFFFFFFu, inc, d);
            if (t >= d) inc += x;
        }
        int exc = inc - sum;
        s_off[4 * t] = exc;
        s_off[4 * t + 1] = exc + v0;
        s_off[4 * t + 2] = exc + v0 + v1;
        s_off[4 * t + 3] = exc + v0 + v1 + v2;
        if (t == 31) s_total = inc;
    }
    __syncthreads();

    if (t < WORDS) {
        int pos = s_off[t];
        uint32_t m = word;
        while (m) {
            int bit = __ffs(m) - 1;
            m &= m - 1;
            s_nbr[pos++] = t * 32 + bit;
        }
    }
    __syncthreads();

    const int n = s_total;
    const float inv = 1.0f / ((float)n + 1e-6f);
    const __half* __restrict__ xb = g_xt + (size_t)b * NN * FC + f8;

    float a0 = 0.f, a1 = 0.f, a2 = 0.f, a3 = 0.f;
    float a4 = 0.f, a5 = 0.f, a6 = 0.f, a7 = 0.f;

#define ACC8(v)                                               \
    do { const __half2* _h = (const __half2*)&(v); float2 _p; \
        _p = __half22float2(_h[0]); a0 += _p.x; a1 += _p.y;   \
        _p = __half22float2(_h[1]); a2 += _p.x; a3 += _p.y;   \
        _p = __half22float2(_h[2]); a4 += _p.x; a5 += _p.y;   \
        _p = __half22float2(_h[3]); a6 += _p.x; a7 += _p.y; } while (0)

    int k = 0;
    for (; k + 4 <= n; k += 4) {
        uint4 v0 = *(const uint4*)&xb[(size_t)s_nbr[k]     * FC];
        uint4 v1 = *(const uint4*)&xb[(size_t)s_nbr[k + 1] * FC];
        uint4 v2 = *(const uint4*)&xb[(size_t)s_nbr[k + 2] * FC];
        uint4 v3 = *(const uint4*)&xb[(size_t)s_nbr[k + 3] * FC];
        ACC8(v0); ACC8(v1); ACC8(v2); ACC8(v3);
    }
    for (; k < n; k++) {
        uint4 v0 = *(const uint4*)&xb[(size_t)s_nbr[k] * FC];
        ACC8(v0);
    }
#undef ACC8

    float4 bl = *(const float4*)&bias[f8];
    float4 bh = *(const float4*)&bias[f8 + 4];
    float* o = out + ((size_t)b * NN + i) * FC + f8;
    *(float4*)o       = make_float4(a0 * inv + bl.x, a1 * inv + bl.y,
                                    a2 * inv + bl.z, a3 * inv + bl.w);
    *(float4*)(o + 4) = make_float4(a4 * inv + bh.x, a5 * inv + bh.y,
                                    a6 * inv + bh.z, a7 * inv + bh.w);
}

// =================== launch ===================
extern "C" void kernel_launch(void* const* d_in, const int* in_sizes, int n_in,
                              void* d_out, int out_size) {
    const float* x    = (const float*)d_in[0];
    const int*   ei   = (const int*)d_in[1];
    const float* w    = (const float*)d_in[2];
    const float* bias = (const float*)d_in[3];
    float*       out  = (float*)d_out;

    const int E = in_sizes[1] / 2;
    const int M = BB * NN;

    cudaFuncSetAttribute(k_gemm, cudaFuncAttributeMaxDynamicSharedMemorySize,
                         GEMM_SMEM);

    k_clear_adj<<<(NN * WORDS + 255) / 256, 256>>>();
    k_scatter<<<(E + 255) / 256, 256>>>(ei, E);
    {
        dim3 tb(32, 8);
        dim3 tg(FC / 32, FC / 32);
        k_wt<<<tg, tb>>>(w);
    }

    dim3 ggrid(M / BM, FC / BN);
    k_gemm<<<ggrid, 256, GEMM_SMEM>>>(x);

    k_aggregate<<<NN, 256>>>(bias, out);
}

// round 7
// speedup vs baseline: 1.0837x; 1.0837x over previous
#include <cuda_runtime.h>
#include <cuda_fp16.h>
#include <stdint.h>

#define NN 4096
#define FC 256      // F_IN == F_OUT
#define BB 8
#define WORDS (NN / 32)

// ---------------- scratch (no allocations allowed) ----------------
__device__ uint32_t g_adj[NN * WORDS];            // 2 MB bitmask adjacency
__device__ __half   g_xt[(size_t)BB * NN * FC];   // 16 MB: xt = x @ W (fp16)
__device__ __half   g_xh[(size_t)BB * NN * FC];   // 16 MB: x as fp16
__device__ __half   g_wh[FC * FC];                // 128 KB: W^T as fp16 [n][k]

// =================== setup kernels ===================
__global__ void k_clear_adj() {
    int i = blockIdx.x * blockDim.x + threadIdx.x;
    if (i < NN * WORDS) g_adj[i] = 0u;
}
__global__ void k_scatter(const int* __restrict__ ei, int E) {
    int e = blockIdx.x * blockDim.x + threadIdx.x;
    if (e < E) {
        int src = ei[e];
        int dst = ei[E + e];
        atomicOr(&g_adj[src * WORDS + (dst >> 5)], 1u << (dst & 31));
    }
}
// W[k][n] -> g_wh[n][k] fp16 (tiled transpose, coalesced)
__global__ void k_wt(const float* __restrict__ W) {
    __shared__ float tile[32][33];
    const int bn = blockIdx.x * 32;
    const int bk = blockIdx.y * 32;
    const int tx = threadIdx.x, ty = threadIdx.y;
#pragma unroll
    for (int r = ty; r < 32; r += 8)
        tile[r][tx] = W[(size_t)(bk + r) * FC + bn + tx];
    __syncthreads();
#pragma unroll
    for (int r = ty; r < 32; r += 8)
        g_wh[(size_t)(bn + r) * FC + bk + tx] = __float2half_rn(tile[tx][r]);
}
// x (fp32) -> g_xh (fp16), streaming
__global__ __launch_bounds__(256) void k_cvt(const float* __restrict__ x) {
    const size_t i = ((size_t)blockIdx.x * 256 + threadIdx.x) * 8;
    float4 v0 = *(const float4*)&x[i];
    float4 v1 = *(const float4*)&x[i + 4];
    __half2 h0 = __floats2half2_rn(v0.x, v0.y);
    __half2 h1 = __floats2half2_rn(v0.z, v0.w);
    __half2 h2 = __floats2half2_rn(v1.x, v1.y);
    __half2 h3 = __floats2half2_rn(v1.z, v1.w);
    *(uint4*)&g_xh[i] = make_uint4(*(uint32_t*)&h0, *(uint32_t*)&h1,
                                   *(uint32_t*)&h2, *(uint32_t*)&h3);
}

// =================== mma / cp.async / ldmatrix helpers ===================
__device__ __forceinline__ void mma_f16(float* d, const uint32_t* a, const uint32_t* b) {
    asm volatile(
        "mma.sync.aligned.m16n8k16.row.col.f32.f16.f16.f32 "
        "{%0,%1,%2,%3}, {%4,%5,%6,%7}, {%8,%9}, {%0,%1,%2,%3};"
        : "+f"(d[0]), "+f"(d[1]), "+f"(d[2]), "+f"(d[3])
        : "r"(a[0]), "r"(a[1]), "r"(a[2]), "r"(a[3]),
          "r"(b[0]), "r"(b[1]));
}
__device__ __forceinline__ uint32_t smem_u32(const void* p) {
    uint32_t a;
    asm("{ .reg .u64 t; cvta.to.shared.u64 t, %1; cvt.u32.u64 %0, t; }" : "=r"(a) : "l"(p));
    return a;
}
#define LDSM_X4(r0, r1, r2, r3, addr)                                        \
    asm volatile("ldmatrix.sync.aligned.m8n8.x4.shared.b16 {%0,%1,%2,%3}, [%4];" \
        : "=r"(r0), "=r"(r1), "=r"(r2), "=r"(r3) : "r"(addr))
#define CP_ASYNC16(dst, src) \
    asm volatile("cp.async.cg.shared.global [%0], [%1], 16;" :: "r"(dst), "l"(src))
#define CP_COMMIT() asm volatile("cp.async.commit_group;" ::: "memory")
#define CP_WAIT0()  asm volatile("cp.async.wait_group 0;" ::: "memory")
#define CP_WAIT1()  asm volatile("cp.async.wait_group 1;" ::: "memory")

// =================== kernel: xt = xh @ Wh  (fp16 mma + ldmatrix, BK=64) ===================
// Tiles: 128x128, BK=64 (rows = 128B -> SW128-style XOR swizzle, conflict-free
// for both cp.async STS16 and ldmatrix LDS16). 2-stage cp.async pipeline.
#define BM 128
#define BN 128
#define BK 64
#define NCH (FC / BK)            // 4
#define TILE_B  (128 * 128)      // 16 KB per (A or B) tile
#define STAGE_B (2 * TILE_B)     // 32 KB
#define A_OFF(p) ((p) * STAGE_B)
#define B_OFF(p) ((p) * STAGE_B + TILE_B)
#define GEMM_SMEM (2 * STAGE_B)  // 64 KB

__global__ __launch_bounds__(256, 2) void k_gemm() {
    extern __shared__ char sm[];
    const uint32_t sb = smem_u32(sm);

    const int tid  = threadIdx.x;
    const int lane = tid & 31;
    const int wid  = tid >> 5;
    const int wm = (wid & 1) * 64;    // warp m-offset (2 warps in m)
    const int wn = (wid >> 1) * 32;   // warp n-offset (4 warps in n)
    const int bm = blockIdx.x * BM;
    const int bn = blockIdx.y * BN;
    const int g  = lane >> 2;
    const int tg = lane & 3;

    // cp.async mapping: id = q*256 + tid; row = id>>3 (128 rows), 16B chunk = id&7
    const int cp_row = tid >> 3;
    const int cp_c   = tid & 7;

    // ldmatrix per-lane row/chunk terms (A: 16-row groups, B: 8-row pairs)
    const int a_lrow  = lane & 15;        // row within m16
    const int a_lchnk = lane >> 4;        // 0/1 -> k chunk parity
    const int b_lrow  = ((lane >> 4) << 3) + (lane & 7);  // row within n16
    const int b_lchnk = (lane >> 3) & 1;  // 0/1 -> k chunk parity

    float acc[4][4][4];
#pragma unroll
    for (int mt = 0; mt < 4; mt++)
#pragma unroll
        for (int nt = 0; nt < 4; nt++)
#pragma unroll
            for (int r = 0; r < 4; r++) acc[mt][nt][r] = 0.0f;

    auto issue = [&](int c, int p) {
        const int k0 = c * BK;
#pragma unroll
        for (int q = 0; q < 4; q++) {          // A: 128 rows x 64 halves
            int row = q * 32 + cp_row;
            uint32_t dst = sb + A_OFF(p) + row * 128 + ((cp_c ^ (row & 7)) << 4);
            CP_ASYNC16(dst, &g_xh[(size_t)(bm + row) * FC + k0 + cp_c * 8]);
        }
#pragma unroll
        for (int q = 0; q < 4; q++) {          // B: 128 rows x 64 halves
            int row = q * 32 + cp_row;
            uint32_t dst = sb + B_OFF(p) + row * 128 + ((cp_c ^ (row & 7)) << 4);
            CP_ASYNC16(dst, &g_wh[(size_t)(bn + row) * FC + k0 + cp_c * 8]);
        }
        CP_COMMIT();
    };

    issue(0, 0);
    issue(1, 1);

#pragma unroll
    for (int c = 0; c < NCH; c++) {
        const int p = c & 1;
        if (c == NCH - 1) { CP_WAIT0(); } else { CP_WAIT1(); }
        __syncthreads();

        const uint32_t sA = sb + A_OFF(p);
        const uint32_t sB = sb + B_OFF(p);

#pragma unroll
        for (int s = 0; s < 4; s++) {          // 4 x K16 per BK=64 chunk
            uint32_t a[4][4], b[4][2];
#pragma unroll
            for (int mt = 0; mt < 4; mt++) {   // A frags: m16k16 via ldmatrix.x4
                int row = wm + mt * 16 + a_lrow;
                int ch  = (s * 2 + a_lchnk) ^ (row & 7);
                LDSM_X4(a[mt][0], a[mt][1], a[mt][2], a[mt][3],
                        sA + row * 128 + (ch << 4));
            }
#pragma unroll
            for (int pr = 0; pr < 2; pr++) {   // B frags: 2 x (n16k16 -> 2 nt)
                int row = wn + pr * 16 + b_lrow;
                int ch  = (s * 2 + b_lchnk) ^ (row & 7);
                LDSM_X4(b[pr * 2][0], b[pr * 2][1], b[pr * 2 + 1][0], b[pr * 2 + 1][1],
                        sB + row * 128 + (ch << 4));
            }
#pragma unroll
            for (int mt = 0; mt < 4; mt++)
#pragma unroll
                for (int nt = 0; nt < 4; nt++)
                    mma_f16(acc[mt][nt], a[mt], b[nt]);
        }
        __syncthreads();
        if (c + 2 < NCH) issue(c + 2, p);
    }

    // ---- epilogue: fp32 acc -> fp16 g_xt ----
#pragma unroll
    for (int mt = 0; mt < 4; mt++) {
#pragma unroll
        for (int nt = 0; nt < 4; nt++) {
            int r = bm + wm + mt * 16 + g;
            int c = bn + wn + nt * 8 + tg * 2;
            __half2 h01 = __floats2half2_rn(acc[mt][nt][0], acc[mt][nt][1]);
            __half2 h23 = __floats2half2_rn(acc[mt][nt][2], acc[mt][nt][3]);
            *(__half2*)&g_xt[(size_t)r * FC + c]       = h01;
            *(__half2*)&g_xt[(size_t)(r + 8) * FC + c] = h23;
        }
    }
}

// =================== kernel: aggregate ===================
// thread t: batch b = t>>5, features f8 = (t&31)*8 (one LDG.128 / neighbor)
__global__ __launch_bounds__(256) void k_aggregate(const float* __restrict__ bias,
                                                   float* __restrict__ out) {
    __shared__ int s_nbr[NN];
    __shared__ int s_off[WORDS];
    __shared__ int s_total;

    const int i = blockIdx.x;
    const int t = threadIdx.x;
    const int b  = t >> 5;
    const int f8 = (t & 31) * 8;

    uint32_t word = (t < WORDS) ? g_adj[i * WORDS + t] : 0u;
    if (t < WORDS) s_off[t] = __popc(word);
    __syncthreads();

    if (t < 32) {   // warp 0: exclusive scan of 128 popcounts
        int v0 = s_off[4 * t], v1 = s_off[4 * t + 1];
        int v2 = s_off[4 * t + 2], v3 = s_off[4 * t + 3];
        int sum = v0 + v1 + v2 + v3;
        int inc = sum;
#pragma unroll
        for (int d = 1; d < 32; d <<= 1) {
            int x = __shfl_up_sync(0xFFFFFFFFu, inc, d);
            if (t >= d) inc += x;
        }
        int exc = inc - sum;
        s_off[4 * t] = exc;
        s_off[4 * t + 1] = exc + v0;
        s_off[4 * t + 2] = exc + v0 + v1;
        s_off[4 * t + 3] = exc + v0 + v1 + v2;
        if (t == 31) s_total = inc;
    }
    __syncthreads();

    if (t < WORDS) {
        int pos = s_off[t];
        uint32_t m = word;
        while (m) {
            int bit = __ffs(m) - 1;
            m &= m - 1;
            s_nbr[pos++] = t * 32 + bit;
        }
    }
    __syncthreads();

    const int n = s_total;
    const float inv = 1.0f / ((float)n + 1e-6f);
    const __half* __restrict__ xb = g_xt + (size_t)b * NN * FC + f8;

    float a0 = 0.f, a1 = 0.f, a2 = 0.f, a3 = 0.f;
    float a4 = 0.f, a5 = 0.f, a6 = 0.f, a7 = 0.f;

#define ACC8(v)                                               \
    do { const __half2* _h = (const __half2*)&(v); float2 _p; \
        _p = __half22float2(_h[0]); a0 += _p.x; a1 += _p.y;   \
        _p = __half22float2(_h[1]); a2 += _p.x; a3 += _p.y;   \
        _p = __half22float2(_h[2]); a4 += _p.x; a5 += _p.y;   \
        _p = __half22float2(_h[3]); a6 += _p.x; a7 += _p.y; } while (0)

    int k = 0;
    for (; k + 4 <= n; k += 4) {
        uint4 v0 = *(const uint4*)&xb[(size_t)s_nbr[k]     * FC];
        uint4 v1 = *(const uint4*)&xb[(size_t)s_nbr[k + 1] * FC];
        uint4 v2 = *(const uint4*)&xb[(size_t)s_nbr[k + 2] * FC];
        uint4 v3 = *(const uint4*)&xb[(size_t)s_nbr[k + 3] * FC];
        ACC8(v0); ACC8(v1); ACC8(v2); ACC8(v3);
    }
    for (; k < n; k++) {
        uint4 v0 = *(const uint4*)&xb[(size_t)s_nbr[k] * FC];
        ACC8(v0);
    }
#undef ACC8

    float4 bl = *(const float4*)&bias[f8];
    float4 bh = *(const float4*)&bias[f8 + 4];
    float* o = out + ((size_t)b * NN + i) * FC + f8;
    *(float4*)o       = make_float4(a0 * inv + bl.x, a1 * inv + bl.y,
                                    a2 * inv + bl.z, a3 * inv + bl.w);
    *(float4*)(o + 4) = make_float4(a4 * inv + bh.x, a5 * inv + bh.y,
                                    a6 * inv + bh.z, a7 * inv + bh.w);
}

// =================== launch ===================
extern "C" void kernel_launch(void* const* d_in, const int* in_sizes, int n_in,
                              void* d_out, int out_size) {
    const float* x    = (const float*)d_in[0];
    const int*   ei   = (const int*)d_in[1];
    const float* w    = (const float*)d_in[2];
    const float* bias = (const float*)d_in[3];
    float*       out  = (float*)d_out;

    const int E = in_sizes[1] / 2;
    const int M = BB * NN;

    cudaFuncSetAttribute(k_gemm, cudaFuncAttributeMaxDynamicSharedMemorySize,
                         GEMM_SMEM);

    k_clear_adj<<<(NN * WORDS + 255) / 256, 256>>>();
    k_scatter<<<(E + 255) / 256, 256>>>(ei, E);
    {
        dim3 tb(32, 8);
        dim3 tg(FC / 32, FC / 32);
        k_wt<<<tg, tb>>>(w);
    }
    k_cvt<<<(int)(((size_t)M * FC / 8 + 255) / 256), 256>>>(x);

    dim3 ggrid(M / BM, FC / BN);
    k_gemm<<<ggrid, 256, GEMM_SMEM>>>();

    k_aggregate<<<NN, 256>>>(bias, out);
}